// round 9
// baseline (speedup 1.0000x reference)
#include <cuda_runtime.h>
#include <cstdint>

#define WW 640
#define HH 480
#define HWPX (WW*HH)           // 307200
#define NB 8
#define NG 368640              // B*H*W*0.15
#define NTOT (NB*NG)           // 2949120  (= 11520 * 256 exactly)
#define NBIN 32768             // top 15 bits of positive float (8 exp + 7 mant)

// Scratch (static __device__ — no allocation allowed)
static __device__ __align__(16) float g_gt_t[HWPX*NB];   // [pix][b]
static __device__ __align__(16) float g_pd_t[HWPX*NB];
static __device__ unsigned g_cnt[NBIN];
static __device__ float    g_sumb[NBIN];
static __device__ unsigned g_blk_cnt[32];
static __device__ double   g_blk_sum[32];

// ---------------------------------------------------------------------------
// Fused: transpose [B,H,W] -> [H*W, B]  +  zero the 32768-bin histogram.
__global__ void k_init(const float* __restrict__ gt, const float* __restrict__ pd) {
    int pix = blockIdx.x*blockDim.x + threadIdx.x;
    if (pix < NBIN) { g_cnt[pix] = 0u; g_sumb[pix] = 0.0f; }
    if (pix >= HWPX) return;
    float v[NB], w[NB];
#pragma unroll
    for (int b = 0; b < NB; b++) {
        v[b] = __ldg(gt + b*HWPX + pix);
        w[b] = __ldg(pd + b*HWPX + pix);
    }
    float4* o = reinterpret_cast<float4*>(g_gt_t + (size_t)pix*NB);
    o[0] = make_float4(v[0], v[1], v[2], v[3]);
    o[1] = make_float4(v[4], v[5], v[6], v[7]);
    float4* p = reinterpret_cast<float4*>(g_pd_t + (size_t)pix*NB);
    p[0] = make_float4(w[0], w[1], w[2], w[3]);
    p[1] = make_float4(w[4], w[5], w[6], w[7]);
}

// FMA-only rsqrt (keeps MUFU pipe empty; 3 Newton steps -> ~1e-7 rel err)
__device__ __forceinline__ float fast_rsqrt_pos(float x) {
    float y = __uint_as_float(0x5f37599eu - (__float_as_uint(x) >> 1));
    float xh = 0.5f * x;
    y = y * (1.5f - xh*y*y);
    y = y * (1.5f - xh*y*y);
    y = y * (1.5f - xh*y*y);
    return y;
}

// One thread per (group, batch) pair. 8 consecutive threads share a group and
// read consecutive floats of the [pix][b] layout (1 sector per point/array).
// Histogram (count + float sum) accumulated straight into global bins.
__global__ void __launch_bounds__(256) k_compute(
        const int* __restrict__ p1x, const int* __restrict__ p1y,
        const int* __restrict__ p2x, const int* __restrict__ p2y,
        const int* __restrict__ p3x, const int* __restrict__ p3y) {
    int tid = blockIdx.x*blockDim.x + threadIdx.x;   // NTOT threads exactly
    int g = tid >> 3;
    int b = tid & 7;

    const float INV_F = 1.0f/519.0f;
    int x1 = p1x[g], y1 = p1y[g];
    int x2 = p2x[g], y2 = p2y[g];
    int x3 = p3x[g], y3 = p3y[g];
    float u1 = ((float)x1 - 320.0f)*INV_F, v1 = ((float)y1 - 240.0f)*INV_F;
    float u2 = ((float)x2 - 320.0f)*INV_F, v2 = ((float)y2 - 240.0f)*INV_F;
    float u3 = ((float)x3 - 320.0f)*INV_F, v3 = ((float)y3 - 240.0f)*INV_F;
    int o1 = (y1*WW + x1)*NB + b;
    int o2 = (y2*WW + x2)*NB + b;
    int o3 = (y3*WW + x3)*NB + b;

    float d1 = g_gt_t[o1], d2 = g_gt_t[o2], d3 = g_gt_t[o3];
    float q1 = g_pd_t[o1], q2 = g_pd_t[o2], q3 = g_pd_t[o3];

    // GT 3D points
    float A1x = u1*fabsf(d1), A1y = v1*fabsf(d1), A1z = d1;
    float A2x = u2*fabsf(d2), A2y = v2*fabsf(d2), A2z = d2;
    float A3x = u3*fabsf(d3), A3y = v3*fabsf(d3), A3z = d3;
    // D rows: d12, d13, d23
    float ax = A2x-A1x, ay = A2y-A1y, az = A2z-A1z;
    float bx = A3x-A1x, by = A3y-A1y, bz = A3z-A1z;
    float cx = A3x-A2x, cy = A3y-A2y, cz = A3z-A2z;
    float e11 = ax*ax+ay*ay+az*az;
    float e22 = bx*bx+by*by+bz*bz;
    float e33 = cx*cx+cy*cy+cz*cz;
    float e12 = ax*bx+ay*by+az*bz;
    float e13 = ax*cx+ay*cy+az*cz;
    float e23 = bx*cx+by*cy+bz*cz;
    // |e_ii/(n_i^2+1e-8)| > 0.867  <=>  e_ii > 0.867e-8/0.133
    const float DIAG_T = 6.518797e-8f;
    const float C2 = 0.751689f;  // 0.867^2
    int cnt = 0;
    cnt += (e11 > DIAG_T) ? 1 : 0;
    cnt += (e22 > DIAG_T) ? 1 : 0;
    cnt += (e33 > DIAG_T) ? 1 : 0;
    cnt += (e12*e12 > C2*e11*e22) ? 2 : 0;
    cnt += (e13*e13 > C2*e11*e33) ? 2 : 0;
    cnt += (e23*e23 > C2*e22*e33) ? 2 : 0;
    bool mcos = cnt > 3;
    bool mx = (fabsf(ax) < 0.01f) | (fabsf(bx) < 0.01f) | (fabsf(cx) < 0.01f);
    bool my = (fabsf(ay) < 0.01f) | (fabsf(by) < 0.01f) | (fabsf(cy) < 0.01f);
    bool mz = (fabsf(az) < 0.01f) | (fabsf(bz) < 0.01f) | (fabsf(cz) < 0.01f);
    bool keep = !((mx & my & mz) | mcos);

    // Pred 3D points (replicating the reference's zmask coord/point mixup)
    float B1x = u1*fabsf(q1), B1y = v1*fabsf(q1), B1z = q1;
    float B2x = u2*fabsf(q2), B2y = v2*fabsf(q2), B2z = q2;
    float B3x = u3*fabsf(q3), B3y = v3*fabsf(q3), B3z = q3;
    if (q1 == 0.0f) { B1x = 1e-4f; B2x = 1e-4f; B3x = 1e-4f; }
    if (q2 == 0.0f) { B1y = 1e-4f; B2y = 1e-4f; B3y = 1e-4f; }
    if (q3 == 0.0f) { B1z = 1e-4f; B2z = 1e-4f; B3z = 1e-4f; }
    float px_ = B2x-B1x, py_ = B2y-B1y, pz_ = B2z-B1z;
    float qx_ = B3x-B1x, qy_ = B3y-B1y, qz_ = B3z-B1z;

    float gnx = ay*bz - az*by;
    float gny = az*bx - ax*bz;
    float gnz = ax*by - ay*bx;
    float dnx = py_*qz_ - pz_*qy_;
    float dny = pz_*qx_ - px_*qz_;
    float dnz = px_*qy_ - py_*qx_;
    float gg = gnx*gnx + gny*gny + gnz*gnz;
    float dd = dnx*dnx + dny*dny + dnz*dnz;
    float rg, rd;
    if (gg >= 1.1754944e-38f)      rg = fast_rsqrt_pos(gg);
    else if (gg > 0.0f)            rg = 1.0f/sqrtf(gg);   // cold path
    else                           rg = 0.0f;             // ref: 0 / 0.01
    if (dd >= 1.1754944e-38f)      rd = fast_rsqrt_pos(dd);
    else if (dd > 0.0f)            rd = 1.0f/sqrtf(dd);
    else                           rd = 0.0f;
    float L = fabsf(gnx*rg - dnx*rd) + fabsf(gny*rg - dny*rd) + fabsf(gnz*rg - dnz*rd);

    if (keep) {
        unsigned bin = __float_as_uint(L) >> 16;   // 0..32767 (L >= 0)
        atomicAdd(&g_sumb[bin], L);                // RED.F32, no return
        unsigned am = __activemask();
        unsigned peers = __match_any_sync(am, bin);
        if ((threadIdx.x & 31) == (unsigned)(__ffs(peers) - 1))
            atomicAdd(&g_cnt[bin], (unsigned)__popc(peers));
    }
}

// 32 blocks; block b reduces bins [b*1024, (b+1)*1024) -> one (count, sum) pair.
__global__ void k_reduce() {
    __shared__ unsigned wc[8];
    __shared__ double wsd[8];
    int base = blockIdx.x * 1024;
    int t = threadIdx.x;                      // 256 threads, 4 bins each (coalesced)
    unsigned c = 0; double s = 0.0;
#pragma unroll
    for (int i = 0; i < 4; i++) {
        int idx = base + t + i*256;
        c += g_cnt[idx];
        s += (double)g_sumb[idx];
    }
#pragma unroll
    for (int o = 16; o; o >>= 1) {
        c += __shfl_down_sync(0xFFFFFFFFu, c, o);
        s += __shfl_down_sync(0xFFFFFFFFu, s, o);
    }
    int wid = t >> 5;
    if ((t & 31) == 0) { wc[wid] = c; wsd[wid] = s; }
    __syncthreads();
    if (t == 0) {
        unsigned ct = 0; double st = 0.0;
        for (int i = 0; i < 8; i++) { ct += wc[i]; st += wsd[i]; }
        g_blk_cnt[blockIdx.x] = ct;
        g_blk_sum[blockIdx.x] = st;
    }
}

// Single block: find boundary block, then boundary bin, compute final loss.
__global__ void k_final(float* out) {
    __shared__ unsigned sc[1024];
    __shared__ double   sd[1024];
    __shared__ int      s_bb;
    __shared__ unsigned s_k, s_aboveCnt;
    __shared__ double   s_aboveSum;
    int t = threadIdx.x;                      // 1024 threads

    if (t == 0) {
        unsigned n = 0;
        for (int i = 0; i < 32; i++) n += g_blk_cnt[i];
        unsigned k = n - (n >> 2);
        s_k = k;
        if (k == 0u) { out[0] = 0.0f; s_bb = -1; }
        else {
            unsigned above = 0; double sab = 0.0;
            int bb = 31;
            while (above + g_blk_cnt[bb] < k) {
                above += g_blk_cnt[bb];
                sab   += g_blk_sum[bb];
                bb--;
            }
            s_bb = bb; s_aboveCnt = above; s_aboveSum = sab;
        }
    }
    __syncthreads();
    int bb = s_bb;
    if (bb < 0) return;
    unsigned k = s_k;

    int bin = bb*1024 + t;
    unsigned c = g_cnt[bin];
    double   s = (double)g_sumb[bin];
    sc[t] = c; sd[t] = s;
    __syncthreads();
    // inclusive suffix scan over the 1024 bins of the boundary block
    for (int off = 1; off < 1024; off <<= 1) {
        unsigned cv = (t + off < 1024) ? sc[t + off] : 0u;
        double   sv = (t + off < 1024) ? sd[t + off] : 0.0;
        __syncthreads();
        sc[t] += cv; sd[t] += sv;
        __syncthreads();
    }
    unsigned incl = s_aboveCnt + sc[t];       // count of values in bins >= bin
    if (incl >= k && (incl - c) < k) {        // boundary bin (exactly one thread)
        unsigned m = k - (incl - c);          // elements taken from this bin
        double tot = s_aboveSum + (sd[t] - s) + ((double)m / (double)c) * s;
        out[0] = (float)(tot / (double)k);
    }
}

// ---------------------------------------------------------------------------
extern "C" void kernel_launch(void* const* d_in, const int* in_sizes, int n_in,
                              void* d_out, int out_size) {
    const float* gt = (const float*)d_in[0];
    const float* pd = (const float*)d_in[1];
    const int* p1x = (const int*)d_in[2];
    const int* p1y = (const int*)d_in[3];
    const int* p2x = (const int*)d_in[4];
    const int* p2y = (const int*)d_in[5];
    const int* p3x = (const int*)d_in[6];
    const int* p3y = (const int*)d_in[7];
    float* out = (float*)d_out;

    k_init<<<(HWPX + 255)/256, 256>>>(gt, pd);
    k_compute<<<NTOT/256, 256>>>(p1x, p1y, p2x, p2y, p3x, p3y);
    k_reduce<<<32, 256>>>();
    k_final<<<1, 1024>>>(out);
}

// round 10
// speedup vs baseline: 2.7321x; 2.7321x over previous
#include <cuda_runtime.h>
#include <cstdint>

#define WW 640
#define HH 480
#define HWPX (WW*HH)           // 307200
#define NB 8
#define NG 368640              // B*H*W*0.15
#define NTOT (NB*NG)           // 2949120  (= 11520 * 256 exactly)
#define H2_BLOCKS 720          // NTOT/4 = 737280 = 720*256*4

// Scratch (static __device__ — no allocation allowed)
static __device__ __align__(16) float g_gt_t[HWPX*NB];   // [pix][b]
static __device__ __align__(16) float g_pd_t[HWPX*NB];
static __device__ __align__(16) float g_L[NTOT];
static __device__ unsigned g_hist1[4096];
static __device__ unsigned g_hist2[4096];
static __device__ float    g_sum2[4096];
static __device__ double g_Shi;
static __device__ unsigned g_k, g_b1, g_m1;
static __device__ unsigned g_ticket;

// ---------------------------------------------------------------------------
// Fused: transpose [B,H,W] -> [H*W, B]  +  zero all selection scratch.
__global__ void k_init(const float* __restrict__ gt, const float* __restrict__ pd) {
    int pix = blockIdx.x*blockDim.x + threadIdx.x;
    if (pix < 4096) { g_hist1[pix] = 0u; g_hist2[pix] = 0u; g_sum2[pix] = 0.0f; }
    if (pix == 0) { g_Shi = 0.0; g_ticket = 0u; }
    if (pix >= HWPX) return;
    float v[NB], w[NB];
#pragma unroll
    for (int b = 0; b < NB; b++) {
        v[b] = __ldg(gt + b*HWPX + pix);
        w[b] = __ldg(pd + b*HWPX + pix);
    }
    float4* o = reinterpret_cast<float4*>(g_gt_t + (size_t)pix*NB);
    o[0] = make_float4(v[0], v[1], v[2], v[3]);
    o[1] = make_float4(v[4], v[5], v[6], v[7]);
    float4* p = reinterpret_cast<float4*>(g_pd_t + (size_t)pix*NB);
    p[0] = make_float4(w[0], w[1], w[2], w[3]);
    p[1] = make_float4(w[4], w[5], w[6], w[7]);
}

// FMA-only rsqrt (keeps MUFU pipe empty; 3 Newton steps -> ~1e-7 rel err)
__device__ __forceinline__ float fast_rsqrt_pos(float x) {
    float y = __uint_as_float(0x5f37599eu - (__float_as_uint(x) >> 1));
    float xh = 0.5f * x;
    y = y * (1.5f - xh*y*y);
    y = y * (1.5f - xh*y*y);
    y = y * (1.5f - xh*y*y);
    return y;
}

// One thread per (group, batch) pair. 8 consecutive threads share a group and
// read consecutive floats of the [pix][b] layout (1 sector per point/array).
// Per-block smem 12-bit histogram -> aggregated global flush. Last block to
// finish also resolves the level-1 boundary bin (k, b1, m1).
__global__ void __launch_bounds__(256) k_compute(
        const int* __restrict__ p1x, const int* __restrict__ p1y,
        const int* __restrict__ p2x, const int* __restrict__ p2y,
        const int* __restrict__ p3x, const int* __restrict__ p3y) {
    __shared__ unsigned sh[4096];
    for (int i = threadIdx.x; i < 4096; i += blockDim.x) sh[i] = 0u;
    __syncthreads();

    int tid = blockIdx.x*blockDim.x + threadIdx.x;   // NTOT threads exactly
    int g = tid >> 3;
    int b = tid & 7;

    const float INV_F = 1.0f/519.0f;
    int x1 = p1x[g], y1 = p1y[g];
    int x2 = p2x[g], y2 = p2y[g];
    int x3 = p3x[g], y3 = p3y[g];
    float u1 = ((float)x1 - 320.0f)*INV_F, v1 = ((float)y1 - 240.0f)*INV_F;
    float u2 = ((float)x2 - 320.0f)*INV_F, v2 = ((float)y2 - 240.0f)*INV_F;
    float u3 = ((float)x3 - 320.0f)*INV_F, v3 = ((float)y3 - 240.0f)*INV_F;
    int o1 = (y1*WW + x1)*NB + b;
    int o2 = (y2*WW + x2)*NB + b;
    int o3 = (y3*WW + x3)*NB + b;

    float d1 = g_gt_t[o1], d2 = g_gt_t[o2], d3 = g_gt_t[o3];
    float q1 = g_pd_t[o1], q2 = g_pd_t[o2], q3 = g_pd_t[o3];

    // GT 3D points
    float A1x = u1*fabsf(d1), A1y = v1*fabsf(d1), A1z = d1;
    float A2x = u2*fabsf(d2), A2y = v2*fabsf(d2), A2z = d2;
    float A3x = u3*fabsf(d3), A3y = v3*fabsf(d3), A3z = d3;
    // D rows: d12, d13, d23
    float ax = A2x-A1x, ay = A2y-A1y, az = A2z-A1z;
    float bx = A3x-A1x, by = A3y-A1y, bz = A3z-A1z;
    float cx = A3x-A2x, cy = A3y-A2y, cz = A3z-A2z;
    float e11 = ax*ax+ay*ay+az*az;
    float e22 = bx*bx+by*by+bz*bz;
    float e33 = cx*cx+cy*cy+cz*cz;
    float e12 = ax*bx+ay*by+az*bz;
    float e13 = ax*cx+ay*cy+az*cz;
    float e23 = bx*cx+by*cy+bz*cz;
    // |e_ii/(n_i^2+1e-8)| > 0.867  <=>  e_ii > 0.867e-8/0.133
    const float DIAG_T = 6.518797e-8f;
    const float C2 = 0.751689f;  // 0.867^2
    int cnt = 0;
    cnt += (e11 > DIAG_T) ? 1 : 0;
    cnt += (e22 > DIAG_T) ? 1 : 0;
    cnt += (e33 > DIAG_T) ? 1 : 0;
    cnt += (e12*e12 > C2*e11*e22) ? 2 : 0;
    cnt += (e13*e13 > C2*e11*e33) ? 2 : 0;
    cnt += (e23*e23 > C2*e22*e33) ? 2 : 0;
    bool mcos = cnt > 3;
    bool mx = (fabsf(ax) < 0.01f) | (fabsf(bx) < 0.01f) | (fabsf(cx) < 0.01f);
    bool my = (fabsf(ay) < 0.01f) | (fabsf(by) < 0.01f) | (fabsf(cy) < 0.01f);
    bool mz = (fabsf(az) < 0.01f) | (fabsf(bz) < 0.01f) | (fabsf(cz) < 0.01f);
    bool keep = !((mx & my & mz) | mcos);

    // Pred 3D points (replicating the reference's zmask coord/point mixup)
    float B1x = u1*fabsf(q1), B1y = v1*fabsf(q1), B1z = q1;
    float B2x = u2*fabsf(q2), B2y = v2*fabsf(q2), B2z = q2;
    float B3x = u3*fabsf(q3), B3y = v3*fabsf(q3), B3z = q3;
    if (q1 == 0.0f) { B1x = 1e-4f; B2x = 1e-4f; B3x = 1e-4f; }
    if (q2 == 0.0f) { B1y = 1e-4f; B2y = 1e-4f; B3y = 1e-4f; }
    if (q3 == 0.0f) { B1z = 1e-4f; B2z = 1e-4f; B3z = 1e-4f; }
    float px_ = B2x-B1x, py_ = B2y-B1y, pz_ = B2z-B1z;
    float qx_ = B3x-B1x, qy_ = B3y-B1y, qz_ = B3z-B1z;

    float gnx = ay*bz - az*by;
    float gny = az*bx - ax*bz;
    float gnz = ax*by - ay*bx;
    float dnx = py_*qz_ - pz_*qy_;
    float dny = pz_*qx_ - px_*qz_;
    float dnz = px_*qy_ - py_*qx_;
    float gg = gnx*gnx + gny*gny + gnz*gnz;
    float dd = dnx*dnx + dny*dny + dnz*dnz;
    float rg, rd;
    if (gg >= 1.1754944e-38f)      rg = fast_rsqrt_pos(gg);
    else if (gg > 0.0f)            rg = 1.0f/sqrtf(gg);   // cold path
    else                           rg = 0.0f;             // ref: 0 / 0.01
    if (dd >= 1.1754944e-38f)      rd = fast_rsqrt_pos(dd);
    else if (dd > 0.0f)            rd = 1.0f/sqrtf(dd);
    else                           rd = 0.0f;
    float L = fabsf(gnx*rg - dnx*rd) + fabsf(gny*rg - dny*rd) + fabsf(gnz*rg - dnz*rd);

    g_L[tid] = keep ? L : -1.0f;
    if (keep) {
        unsigned bin = __float_as_uint(L) >> 20;   // sign+exp+3 mantissa bits
        unsigned am = __activemask();
        unsigned peers = __match_any_sync(am, bin);
        if ((threadIdx.x & 31) == (unsigned)(__ffs(peers) - 1))
            atomicAdd(&sh[bin], (unsigned)__popc(peers));
    }
    __syncthreads();
    for (int i = threadIdx.x; i < 4096; i += blockDim.x) {
        unsigned v = sh[i];
        if (v) atomicAdd(&g_hist1[i], v);
    }

    // ---- last-finishing block resolves (k, b1, m1) from the global hist ----
    __shared__ unsigned s_last;
    __threadfence();
    __syncthreads();
    if (threadIdx.x == 0) s_last = atomicAdd(&g_ticket, 1u);
    __syncthreads();
    if (s_last != gridDim.x - 1) return;
    __threadfence();   // acquire: see all blocks' g_hist1 flushes

    // 3-level reduction using sh[] as scratch: 256 threads, 16 bins each.
    __shared__ unsigned ts[256];
    __shared__ unsigned ws[8];
    int t = threadIdx.x;
    unsigned s = 0;
#pragma unroll
    for (int i = 0; i < 16; i++) {
        unsigned v = g_hist1[t*16 + i];
        sh[t*16 + i] = v;
        s += v;
    }
    ts[t] = s;
#pragma unroll
    for (int o = 16; o; o >>= 1) s += __shfl_down_sync(0xFFFFFFFFu, s, o);
    if ((t & 31) == 0) ws[t >> 5] = s;
    __syncthreads();
    if (t == 0) {
        unsigned n = 0;
        for (int i = 0; i < 8; i++) n += ws[i];
        unsigned drop = n >> 2;
        unsigned k = n - drop;
        g_k = k;
        if (k == 0) { g_b1 = 0xFFFFFFFFu; g_m1 = 0u; return; }
        unsigned above = 0;
        int w = 7;
        while (above + ws[w] < k) { above += ws[w]; w--; }
        int th = w*32 + 31;
        while (above + ts[th] < k) { above += ts[th]; th--; }
        int bin = th*16 + 15;
        while (above + sh[bin] < k) { above += sh[bin]; bin--; }
        g_b1 = (unsigned)bin;
        g_m1 = k - above;
    }
}

// One vectorized pass over g_L: counts + float sums per 24-bit subbin inside
// boundary bin b1, plus the exact sum of everything strictly above bin b1.
__global__ void __launch_bounds__(256) k_hist2() {
    __shared__ unsigned scnt[4096];
    __shared__ float    ssum[4096];
    for (int i = threadIdx.x; i < 4096; i += blockDim.x) { scnt[i] = 0u; ssum[i] = 0.0f; }
    __syncthreads();
    unsigned b1 = g_b1;
    float shi = 0.f;
    int base = blockIdx.x*blockDim.x + threadIdx.x;   // H2_BLOCKS*256 threads
    const float4* L4 = reinterpret_cast<const float4*>(g_L);
#pragma unroll
    for (int j = 0; j < 4; j++) {
        float4 v4 = L4[base + j*(H2_BLOCKS*256)];
        float vv[4] = {v4.x, v4.y, v4.z, v4.w};
#pragma unroll
        for (int e = 0; e < 4; e++) {
            unsigned bits = __float_as_uint(vv[e]);
            if (!(bits >> 31)) {
                unsigned bin12 = bits >> 20;
                if (bin12 > b1) shi += vv[e];
                else if (bin12 == b1) {
                    unsigned sub = (bits >> 8) & 0xFFFu;
                    atomicAdd(&scnt[sub], 1u);
                    atomicAdd(&ssum[sub], vv[e]);
                }
            }
        }
    }
    // reduce shi
#pragma unroll
    for (int o = 16; o; o >>= 1) shi += __shfl_down_sync(0xFFFFFFFFu, shi, o);
    __shared__ float wsum[8];
    int wid = threadIdx.x >> 5;
    if ((threadIdx.x & 31) == 0) wsum[wid] = shi;
    __syncthreads();
    if (threadIdx.x == 0) {
        float a = 0.f;
        for (int i = 0; i < 8; i++) a += wsum[i];
        if (a != 0.f) atomicAdd(&g_Shi, (double)a);
    }
    for (int i = threadIdx.x; i < 4096; i += blockDim.x) {
        unsigned c = scnt[i];
        if (c) { atomicAdd(&g_hist2[i], c); atomicAdd(&g_sum2[i], ssum[i]); }
    }
}

// Find 24-bit key subbin, then finish the whole reduction from subbin sums.
__global__ void k_scan2_final(float* out) {
    __shared__ unsigned h[4096];
    __shared__ unsigned ts[1024];
    __shared__ unsigned ws[32];
    __shared__ int s_key;
    __shared__ double s_frac;
    __shared__ double dred[32];
    int t = threadIdx.x;                 // 1024 threads
    unsigned k = g_k;
    if (k == 0u) { if (t == 0) out[0] = 0.0f; return; }

    unsigned s = 0;
#pragma unroll
    for (int i = 0; i < 4; i++) {
        unsigned v = g_hist2[t*4 + i];
        h[t*4 + i] = v;
        s += v;
    }
    ts[t] = s;
#pragma unroll
    for (int o = 16; o; o >>= 1) s += __shfl_down_sync(0xFFFFFFFFu, s, o);
    if ((t & 31) == 0) ws[t >> 5] = s;
    __syncthreads();
    if (t == 0) {
        unsigned m1 = g_m1;
        unsigned above = 0;
        int w = 31;
        while (above + ws[w] < m1) { above += ws[w]; w--; }
        int th = w*32 + 31;
        while (above + ts[th] < m1) { above += ts[th]; th--; }
        int bin = th*4 + 3;
        while (above + h[bin] < m1) { above += h[bin]; bin--; }
        unsigned m2 = m1 - above;
        unsigned csub = h[bin];
        s_key = bin;
        s_frac = (double)g_sum2[bin] * ((double)m2 / (double)csub);
    }
    __syncthreads();
    int key = s_key;
    // parallel suffix sum of subbin sums strictly above key
    double loc = 0.0;
#pragma unroll
    for (int i = 0; i < 4; i++) {
        int idx = t*4 + i;
        if (idx > key && h[idx]) loc += (double)g_sum2[idx];
    }
#pragma unroll
    for (int o = 16; o; o >>= 1) loc += __shfl_down_sync(0xFFFFFFFFu, loc, o);
    if ((t & 31) == 0) dred[t >> 5] = loc;
    __syncthreads();
    if (t == 0) {
        double tot = s_frac + g_Shi;
        for (int i = 0; i < 32; i++) tot += dred[i];
        out[0] = (float)(tot / (double)k);
    }
}

// ---------------------------------------------------------------------------
extern "C" void kernel_launch(void* const* d_in, const int* in_sizes, int n_in,
                              void* d_out, int out_size) {
    const float* gt = (const float*)d_in[0];
    const float* pd = (const float*)d_in[1];
    const int* p1x = (const int*)d_in[2];
    const int* p1y = (const int*)d_in[3];
    const int* p2x = (const int*)d_in[4];
    const int* p2y = (const int*)d_in[5];
    const int* p3x = (const int*)d_in[6];
    const int* p3y = (const int*)d_in[7];
    float* out = (float*)d_out;

    k_init<<<(HWPX + 255)/256, 256>>>(gt, pd);
    k_compute<<<NTOT/256, 256>>>(p1x, p1y, p2x, p2y, p3x, p3y);
    k_hist2<<<H2_BLOCKS, 256>>>();
    k_scan2_final<<<1, 1024>>>(out);
}